// round 11
// baseline (speedup 1.0000x reference)
#include <cuda_runtime.h>
#include <cstdint>

// ---------------------------------------------------------------------------
// YoloLoss: persistent depth-3 cp.async pipeline (pred staged in smem),
// targ register-prefetched one tile ahead, static strided schedule.
// 128-thr blocks, 11/SM. Epilogue: 64-way spread double accumulators to
// de-serialize same-address L2 atomics; last block (ticket) finalizes.
//   predictions: [Ncells, 13] f32   target: [Ncells, 8] f32  -> scalar f32
// ---------------------------------------------------------------------------

#define LAMBDA_NOOBJ 0.5f
#define LAMBDA_COORD 5.0f
#define IOU_EPS 1e-6f

constexpr int THREADS = 128;
constexpr int CPB = 128;                      // cells per tile (== THREADS)
constexpr int PRED_FLOATS = CPB * 13;         // 1664 floats = 6656 B / stage
constexpr int DEPTH = 3;                      // ring depth (prefetch distance 2)
constexpr int PRED_CHUNKS = PRED_FLOATS / 4;  // 416 x 16B
constexpr int ACC_SLOTS = 64;

__device__ double   g_acc[ACC_SLOTS];   // static zero-init
__device__ unsigned g_done;

__device__ __forceinline__ void cpasync16(uint32_t saddr, const void* gaddr) {
    asm volatile("cp.async.cg.shared.global [%0], [%1], 16;"
                 :: "r"(saddr), "l"(gaddr) : "memory");
}
__device__ __forceinline__ float fdiv_approx(float a, float b) {
    float r; asm("div.approx.f32 %0, %1, %2;" : "=f"(r) : "f"(a), "f"(b)); return r;
}
__device__ __forceinline__ float fsqrt_approx(float a) {
    float r; asm("sqrt.approx.f32 %0, %1;" : "=f"(r) : "f"(a)); return r;
}

__device__ __forceinline__ float iou_f(float ax, float ay, float aw, float ah,
                                       float bx, float by, float bw, float bh) {
    float ax1 = ax - aw * 0.5f, ay1 = ay - ah * 0.5f;
    float ax2 = ax + aw * 0.5f, ay2 = ay + ah * 0.5f;
    float bx1 = bx - bw * 0.5f, by1 = by - bh * 0.5f;
    float bx2 = bx + bw * 0.5f, by2 = by + bh * 0.5f;
    float iw = fmaxf(fminf(ax2, bx2) - fmaxf(ax1, bx1), 0.0f);
    float ih = fmaxf(fminf(ay2, by2) - fmaxf(ay1, by1), 0.0f);
    float inter = iw * ih;
    float uni = (ax2 - ax1) * (ay2 - ay1) + (bx2 - bx1) * (by2 - by1) - inter;
    return fdiv_approx(inter, uni + IOU_EPS);
}

__device__ __forceinline__ float cell_loss(const float* __restrict__ p,
                                           float4 ta, float4 tb) {
    const float t0 = ta.x, tx = ta.y, ty = ta.z, tw = ta.w;
    const float th = tb.x, tc0 = tb.y, tc1 = tb.z, tc2 = tb.w;

    float iou1 = iou_f(p[1], p[2], p[3], p[4], tx, ty, tw, th);
    float iou2 = iou_f(p[6], p[7], p[8], p[9], tx, ty, tw, th);
    bool pick1 = iou1 > iou2;
    float iou = pick1 ? iou1 : iou2;
    float s0 = pick1 ? p[0] : p[5];
    float s1 = pick1 ? p[1] : p[6];
    float s2 = pick1 ? p[2] : p[7];
    float s3 = pick1 ? p[3] : p[8];
    float s4 = pick1 ? p[4] : p[9];
    float u0 = pick1 ? p[5] : p[0];

    float dx = s1 - tx, dy = s2 - ty;
    float loss_xy = dx * dx + dy * dy;

    float w1 = copysignf(fsqrt_approx(fabsf(s3)), s3) - fsqrt_approx(tw);
    float w2 = copysignf(fsqrt_approx(fabsf(s4)), s4) - fsqrt_approx(th);
    float loss_wh = w1 * w1 + w2 * w2;

    float dobj = s0 - iou;
    float loss_obj = dobj * dobj;

    float c0 = p[10] - tc0, c1 = p[11] - tc1, c2 = p[12] - tc2;
    float loss_cls = c0 * c0 + c1 * c1 + c2 * c2;

    float noobj_both = p[0] * p[0] + p[5] * p[5];

    float m = (t0 == 1.0f) ? 1.0f : 0.0f;
    return m * (LAMBDA_COORD * (loss_xy + loss_wh) + loss_obj + loss_cls
                + LAMBDA_NOOBJ * u0 * u0)
         + (1.0f - m) * LAMBDA_NOOBJ * noobj_both;
}

// Stage one tile's predictions into smem (coalesced 16B cp.async).
__device__ __forceinline__ void stage_pred(float* sbuf,
                                           const float* __restrict__ pred,
                                           long long tile) {
    const int tid = threadIdx.x;
    const char* pg = (const char*)(pred + tile * (long long)CPB * 13);
    uint32_t sb = (uint32_t)__cvta_generic_to_shared(sbuf);
    #pragma unroll
    for (int k = 0; k < 3; k++) {
        int i = tid + k * THREADS;
        cpasync16(sb + i * 16, pg + (size_t)i * 16);
    }
    {   int i = tid + 3 * THREADS;               // 416 chunks total
        if (i < PRED_CHUNKS) cpasync16(sb + i * 16, pg + (size_t)i * 16);
    }
}

__global__ void __launch_bounds__(THREADS, 11)
yolo_fused(const float* __restrict__ pred,
           const float* __restrict__ targ,
           float* __restrict__ out,
           long long n_cells, long long n_tiles, double inv_batch, unsigned n_blocks) {
    __shared__ float sp[DEPTH][PRED_FLOATS];     // 19968 B
    __shared__ float wsum[THREADS / 32];

    const int tid = threadIdx.x;
    const long long G = gridDim.x;
    float local = 0.0f;

    // Prologue: prefetch pred for first two tiles + targ regs for first tile.
    long long t = blockIdx.x;
    if (t < n_tiles) stage_pred(sp[0], pred, t);
    asm volatile("cp.async.commit_group;" ::: "memory");
    if (t + G < n_tiles) stage_pred(sp[1], pred, t + G);
    asm volatile("cp.async.commit_group;" ::: "memory");

    float4 ta = make_float4(0.f, 0.f, 0.f, 0.f);
    float4 tb = ta;
    if (t < n_tiles) {
        const float4* tg = reinterpret_cast<const float4*>(targ + (t * CPB + tid) * 8);
        ta = __ldcs(tg);
        tb = __ldcs(tg + 1);
    }

    int buf = 0;
    for (; t < n_tiles; t += G) {
        // This tile's pred group complete; barrier also proves everyone is
        // done reading the slot we're about to overwrite.
        asm volatile("cp.async.wait_group 1;" ::: "memory");
        __syncthreads();

        // Prefetch pred for t+2G into the freed ring slot.
        long long pf = t + 2 * G;
        int nbuf = buf + 2; if (nbuf >= DEPTH) nbuf -= DEPTH;
        if (pf < n_tiles) stage_pred(sp[nbuf], pred, pf);
        asm volatile("cp.async.commit_group;" ::: "memory");

        // Register-prefetch targ for t+G (consumed next iteration).
        float4 nta = make_float4(0.f, 0.f, 0.f, 0.f);
        float4 ntb = nta;
        if (t + G < n_tiles) {
            const float4* tg =
                reinterpret_cast<const float4*>(targ + ((t + G) * CPB + tid) * 8);
            nta = __ldcs(tg);
            ntb = __ldcs(tg + 1);
        }

        // Compute this tile: pred from smem, targ from regs (already resident).
        local += cell_loss(sp[buf] + tid * 13, ta, tb);

        ta = nta; tb = ntb;
        buf += 1; if (buf >= DEPTH) buf -= DEPTH;
    }

    // ---- block reduction ----
    #pragma unroll
    for (int o = 16; o > 0; o >>= 1)
        local += __shfl_down_sync(0xffffffffu, local, o);

    const int lane = tid & 31, warp = tid >> 5;
    if (lane == 0) wsum[warp] = local;
    __syncthreads();

    if (tid == 0) {
        double bsum = 0.0;
        #pragma unroll
        for (int i = 0; i < THREADS / 32; i++) bsum += (double)wsum[i];
        // Spread contention: 64 accumulator slots instead of one.
        atomicAdd(&g_acc[blockIdx.x & (ACC_SLOTS - 1)], bsum);
        __threadfence();
        unsigned ticket = atomicAdd(&g_done, 1u);
        if (ticket == n_blocks - 1u) {
            __threadfence();
            double total = 0.0;
            #pragma unroll
            for (int i = 0; i < ACC_SLOTS; i++) {
                total += __ldcg(&g_acc[i]);   // L2-coherent read
                g_acc[i] = 0.0;               // reset for next graph replay
            }
            out[0] = (float)(total * inv_batch);
            g_done = 0u;
        }
    }
}

extern "C" void kernel_launch(void* const* d_in, const int* in_sizes, int n_in,
                              void* d_out, int out_size) {
    const float* pred = (const float*)d_in[0];
    const float* targ = (const float*)d_in[1];
    float* out = (float*)d_out;

    long long n_cells = (long long)in_sizes[1] / 8;     // target: 8 floats/cell
    long long batch = n_cells / 49;                     // S*S = 49
    long long n_tiles = (n_cells + CPB - 1) / CPB;      // 16504 (exact for this shape)

    unsigned grid = 152u * 11u;                         // 11 blocks/SM @ 20KB smem
    if (grid > (unsigned)n_tiles) grid = (unsigned)n_tiles;

    yolo_fused<<<grid, THREADS>>>(pred, targ, out, n_cells, n_tiles,
                                  1.0 / (double)batch, grid);
}

// round 12
// speedup vs baseline: 1.7601x; 1.7601x over previous
#include <cuda_runtime.h>
#include <cstdint>

// ---------------------------------------------------------------------------
// YoloLoss: persistent depth-3 cp.async pipeline (pred staged in smem),
// targ register-prefetched one tile ahead (LDG.128 x2, consumed next iter).
// Static strided schedule, single global accumulator, last-block finalize.
// Best-measured configuration (R6): 20.54 us = 6.57 TB/s = 82% of HBM spec.
//   predictions: [Ncells, 13] f32   target: [Ncells, 8] f32  -> scalar f32
// ---------------------------------------------------------------------------

#define LAMBDA_NOOBJ 0.5f
#define LAMBDA_COORD 5.0f
#define IOU_EPS 1e-6f

constexpr int THREADS = 256;
constexpr int CPB = 256;                      // cells per tile (== THREADS)
constexpr int PRED_FLOATS = CPB * 13;         // 3328 floats = 13312 B / stage
constexpr int DEPTH = 3;                      // ring depth (prefetch distance 2)
constexpr int PRED_CHUNKS = PRED_FLOATS / 4;  // 832 x 16B

__device__ double   g_acc;     // static zero-init
__device__ unsigned g_done;

__device__ __forceinline__ void cpasync16(uint32_t saddr, const void* gaddr) {
    asm volatile("cp.async.cg.shared.global [%0], [%1], 16;"
                 :: "r"(saddr), "l"(gaddr) : "memory");
}
__device__ __forceinline__ float fdiv_approx(float a, float b) {
    float r; asm("div.approx.f32 %0, %1, %2;" : "=f"(r) : "f"(a), "f"(b)); return r;
}
__device__ __forceinline__ float fsqrt_approx(float a) {
    float r; asm("sqrt.approx.f32 %0, %1;" : "=f"(r) : "f"(a)); return r;
}

__device__ __forceinline__ float iou_f(float ax, float ay, float aw, float ah,
                                       float bx, float by, float bw, float bh) {
    float ax1 = ax - aw * 0.5f, ay1 = ay - ah * 0.5f;
    float ax2 = ax + aw * 0.5f, ay2 = ay + ah * 0.5f;
    float bx1 = bx - bw * 0.5f, by1 = by - bh * 0.5f;
    float bx2 = bx + bw * 0.5f, by2 = by + bh * 0.5f;
    float iw = fmaxf(fminf(ax2, bx2) - fmaxf(ax1, bx1), 0.0f);
    float ih = fmaxf(fminf(ay2, by2) - fmaxf(ay1, by1), 0.0f);
    float inter = iw * ih;
    float uni = (ax2 - ax1) * (ay2 - ay1) + (bx2 - bx1) * (by2 - by1) - inter;
    return fdiv_approx(inter, uni + IOU_EPS);
}

__device__ __forceinline__ float cell_loss(const float* __restrict__ p,
                                           float4 ta, float4 tb) {
    const float t0 = ta.x, tx = ta.y, ty = ta.z, tw = ta.w;
    const float th = tb.x, tc0 = tb.y, tc1 = tb.z, tc2 = tb.w;

    float iou1 = iou_f(p[1], p[2], p[3], p[4], tx, ty, tw, th);
    float iou2 = iou_f(p[6], p[7], p[8], p[9], tx, ty, tw, th);
    bool pick1 = iou1 > iou2;
    float iou = pick1 ? iou1 : iou2;
    float s0 = pick1 ? p[0] : p[5];
    float s1 = pick1 ? p[1] : p[6];
    float s2 = pick1 ? p[2] : p[7];
    float s3 = pick1 ? p[3] : p[8];
    float s4 = pick1 ? p[4] : p[9];
    float u0 = pick1 ? p[5] : p[0];

    float dx = s1 - tx, dy = s2 - ty;
    float loss_xy = dx * dx + dy * dy;

    float w1 = copysignf(fsqrt_approx(fabsf(s3)), s3) - fsqrt_approx(tw);
    float w2 = copysignf(fsqrt_approx(fabsf(s4)), s4) - fsqrt_approx(th);
    float loss_wh = w1 * w1 + w2 * w2;

    float dobj = s0 - iou;
    float loss_obj = dobj * dobj;

    float c0 = p[10] - tc0, c1 = p[11] - tc1, c2 = p[12] - tc2;
    float loss_cls = c0 * c0 + c1 * c1 + c2 * c2;

    float noobj_both = p[0] * p[0] + p[5] * p[5];

    float m = (t0 == 1.0f) ? 1.0f : 0.0f;
    return m * (LAMBDA_COORD * (loss_xy + loss_wh) + loss_obj + loss_cls
                + LAMBDA_NOOBJ * u0 * u0)
         + (1.0f - m) * LAMBDA_NOOBJ * noobj_both;
}

// Stage one tile's predictions into smem (coalesced 16B cp.async).
__device__ __forceinline__ void stage_pred(float* sbuf,
                                           const float* __restrict__ pred,
                                           long long tile) {
    const int tid = threadIdx.x;
    const char* pg = (const char*)(pred + tile * (long long)CPB * 13);
    uint32_t sb = (uint32_t)__cvta_generic_to_shared(sbuf);
    #pragma unroll
    for (int k = 0; k < 3; k++) {
        int i = tid + k * THREADS;
        cpasync16(sb + i * 16, pg + (size_t)i * 16);
    }
    {   int i = tid + 3 * THREADS;               // 832 chunks total
        if (i < PRED_CHUNKS) cpasync16(sb + i * 16, pg + (size_t)i * 16);
    }
}

__global__ void __launch_bounds__(THREADS)
yolo_fused(const float* __restrict__ pred,
           const float* __restrict__ targ,
           float* __restrict__ out,
           long long n_cells, long long n_tiles, double inv_batch, unsigned n_blocks) {
    __shared__ float sp[DEPTH][PRED_FLOATS];     // 39936 B
    __shared__ float wsum[THREADS / 32];

    const int tid = threadIdx.x;
    const long long G = gridDim.x;
    float local = 0.0f;

    // Prologue: prefetch pred for first two tiles + targ regs for first tile.
    long long t = blockIdx.x;
    if (t < n_tiles) stage_pred(sp[0], pred, t);
    asm volatile("cp.async.commit_group;" ::: "memory");
    if (t + G < n_tiles) stage_pred(sp[1], pred, t + G);
    asm volatile("cp.async.commit_group;" ::: "memory");

    float4 ta = make_float4(0.f, 0.f, 0.f, 0.f);
    float4 tb = ta;
    if (t < n_tiles) {
        const float4* tg = reinterpret_cast<const float4*>(targ + (t * CPB + tid) * 8);
        ta = __ldcs(tg);
        tb = __ldcs(tg + 1);
    }

    int buf = 0;
    for (; t < n_tiles; t += G) {
        // This tile's pred group complete; barrier also proves everyone is
        // done reading the slot we're about to overwrite.
        asm volatile("cp.async.wait_group 1;" ::: "memory");
        __syncthreads();

        // Prefetch pred for t+2G into the freed ring slot.
        long long pf = t + 2 * G;
        int nbuf = buf + 2; if (nbuf >= DEPTH) nbuf -= DEPTH;
        if (pf < n_tiles) stage_pred(sp[nbuf], pred, pf);
        asm volatile("cp.async.commit_group;" ::: "memory");

        // Register-prefetch targ for t+G (consumed next iteration).
        float4 nta = make_float4(0.f, 0.f, 0.f, 0.f);
        float4 ntb = nta;
        if (t + G < n_tiles) {
            const float4* tg =
                reinterpret_cast<const float4*>(targ + ((t + G) * CPB + tid) * 8);
            nta = __ldcs(tg);
            ntb = __ldcs(tg + 1);
        }

        // Compute this tile: pred from smem, targ from regs (already resident).
        local += cell_loss(sp[buf] + tid * 13, ta, tb);

        ta = nta; tb = ntb;
        buf += 1; if (buf >= DEPTH) buf -= DEPTH;
    }

    // ---- block reduction ----
    #pragma unroll
    for (int o = 16; o > 0; o >>= 1)
        local += __shfl_down_sync(0xffffffffu, local, o);

    const int lane = tid & 31, warp = tid >> 5;
    if (lane == 0) wsum[warp] = local;
    __syncthreads();

    if (tid == 0) {
        double bsum = 0.0;
        #pragma unroll
        for (int i = 0; i < THREADS / 32; i++) bsum += (double)wsum[i];
        atomicAdd(&g_acc, bsum);
        __threadfence();
        unsigned ticket = atomicAdd(&g_done, 1u);
        if (ticket == n_blocks - 1u) {
            __threadfence();
            double total = atomicAdd(&g_acc, 0.0);
            out[0] = (float)(total * inv_batch);
            g_acc = 0.0;           // reset for next graph replay
            g_done = 0u;
        }
    }
}

extern "C" void kernel_launch(void* const* d_in, const int* in_sizes, int n_in,
                              void* d_out, int out_size) {
    const float* pred = (const float*)d_in[0];
    const float* targ = (const float*)d_in[1];
    float* out = (float*)d_out;

    long long n_cells = (long long)in_sizes[1] / 8;     // target: 8 floats/cell
    long long batch = n_cells / 49;                     // S*S = 49
    long long n_tiles = (n_cells + CPB - 1) / CPB;      // 6272 (exact for this shape)

    unsigned grid = 152u * 5u;                          // 5 blocks/SM @ ~40KB smem
    if (grid > (unsigned)n_tiles) grid = (unsigned)n_tiles;

    yolo_fused<<<grid, THREADS>>>(pred, targ, out, n_cells, n_tiles,
                                  1.0 / (double)batch, grid);
}